// round 5
// baseline (speedup 1.0000x reference)
#include <cuda_runtime.h>
#include <math.h>

#define B_    32
#define FBINS 128
#define TTOT  2400
#define HDIM  256
#define SEG_  24
#define SSEG  100
#define BS_   3200   // B_*SSEG

// ---------------- scratch (device globals: sanctioned scratch mechanism) -----
__device__ float g_xT[B_*TTOT*FBINS];      // (B, T, F) transposed input
__device__ float g_rec[B_*TTOT*FBINS];     // (B, T, F) reconstruction before final transpose
__device__ float g_gates[BS_*1024];        // gate preacts scratch (oe: 3200x1024, od: 3200x512)
__device__ float g_h[BS_*HDIM];            // oe hidden
__device__ float g_c[BS_*HDIM];            // oe cell -> c_seg
__device__ float g_xw_ie[BS_*1024];
__device__ float g_bot[B_*HDIM];           // bottleneck (final cell of ie)
__device__ float g_xw_id[B_*1024];
__device__ float g_dec[BS_*HDIM];          // inner-decoder hidden states (B,S,H)
__device__ float g_xw_od[BS_*512];
__device__ float g_h2[BS_*FBINS];          // od hidden
__device__ float g_c2[BS_*FBINS];          // od cell
// transposed weights / fused biases
__device__ float g_oe_wT[(FBINS+HDIM)*1024];   // rows 0..127: WihT, 128..383: WhhT
__device__ float g_oe_b[1024];
__device__ float g_ie_wihT[HDIM*1024];
__device__ float g_ie_b[1024];
__device__ float g_id_wihT[HDIM*1024];
__device__ float g_id_b[1024];
__device__ float g_od_wihT[HDIM*512];
__device__ float g_od_whhT[FBINS*512];
__device__ float g_od_b[512];
__device__ float4 g_ie_wp[HDIM*HDIM];      // wp[k*256+u] = (Wi[u][k],Wf[u][k],Wg[u][k],Wo[u][k])
__device__ float4 g_id_wp[HDIM*HDIM];

__device__ __forceinline__ float sigf(float x) { return 1.0f / (1.0f + expf(-x)); }

// ---------------- batched tiled transpose: src (batch, R, C) -> dst (batch, C, R)
__global__ void btrans(float* __restrict__ dst, const float* __restrict__ src, int R, int C) {
    __shared__ float tile[32][33];
    int b  = blockIdx.z;
    int c0 = blockIdx.x * 32, r0 = blockIdx.y * 32;
    const float* s = src + (size_t)b * R * C;
    float*       d = dst + (size_t)b * R * C;
    int tx = threadIdx.x, ty = threadIdx.y;   // 32 x 8
    #pragma unroll
    for (int i = 0; i < 32; i += 8) {
        int r = r0 + ty + i, c = c0 + tx;
        if (r < R && c < C) tile[ty + i][tx] = s[r * C + c];
    }
    __syncthreads();
    #pragma unroll
    for (int i = 0; i < 32; i += 8) {
        int c = c0 + ty + i, r = r0 + tx;
        if (c < C && r < R) d[c * R + r] = tile[tx][ty + i];
    }
}

// ---------------- pack recurrent weights for inner LSTMs: float4 per (k,u) ----
__global__ void pack_whh(float4* __restrict__ dst, const float* __restrict__ whh) {
    int idx = blockIdx.x * blockDim.x + threadIdx.x;   // 65536
    if (idx >= HDIM * HDIM) return;
    int k = idx >> 8, u = idx & 255;
    dst[idx] = make_float4(whh[(0   + u) * HDIM + k],
                           whh[(256 + u) * HDIM + k],
                           whh[(512 + u) * HDIM + k],
                           whh[(768 + u) * HDIM + k]);
}

// ---------------- fused biases b_ih + b_hh ----------------------------------
__global__ void prep_biases(const float* oe1, const float* oe2,
                            const float* ie1, const float* ie2,
                            const float* id1, const float* id2,
                            const float* od1, const float* od2,
                            float* oeb, float* ieb, float* idb, float* odb) {
    int i = blockIdx.x * blockDim.x + threadIdx.x;
    if (i < 1024) {
        oeb[i] = oe1[i] + oe2[i];
        ieb[i] = ie1[i] + ie2[i];
        idb[i] = id1[i] + id2[i];
    }
    if (i < 512) odb[i] = od1[i] + od2[i];
}

// ---------------- generic gate GEMM -----------------------------------------
// G[m][n] = (Rm? Rm[m][n] : bias? bias[n] : 0)
//         + sum_{k<K1} A1[m*lda1+k]*WT[k][n] + sum_{k<K2} A2[m*lda2+k]*WT[K1+k][n]
// Tiles: 64x64, BK=16, 256 threads, 4x4 per thread.
__global__ void __launch_bounds__(256)
gemm_gates(int M, int N,
           const float* __restrict__ A1, int lda1, int K1,
           const float* __restrict__ A2, int lda2, int K2,
           const float* __restrict__ WT,
           const float* __restrict__ bias,
           const float* __restrict__ Rm,
           float* __restrict__ G) {
    __shared__ __align__(16) float As[16][68];
    __shared__ __align__(16) float Bs[16][64];
    const int tid = threadIdx.x;
    const int bn = blockIdx.x * 64;
    const int bm = blockIdx.y * 64;
    const int tx = tid & 15;
    const int ty = tid >> 4;
    const int ar = tid >> 2;          // A row within tile (0..63)
    const int ak = (tid & 3) * 4;     // A k-offset (0,4,8,12)
    const int brow = tid >> 4;        // B k row (0..15)
    const int bcol = (tid & 15) * 4;  // B n offset

    float acc[4][4];
    #pragma unroll
    for (int i = 0; i < 4; i++)
        #pragma unroll
        for (int j = 0; j < 4; j++) acc[i][j] = 0.0f;

    const int K = K1 + K2;
    for (int k0 = 0; k0 < K; k0 += 16) {
        // --- load A tile
        int row = bm + ar;
        float4 av = make_float4(0.f, 0.f, 0.f, 0.f);
        if (row < M) {
            if (k0 < K1) av = *reinterpret_cast<const float4*>(A1 + (size_t)row * lda1 + k0 + ak);
            else         av = *reinterpret_cast<const float4*>(A2 + (size_t)row * lda2 + (k0 - K1) + ak);
        }
        As[ak + 0][ar] = av.x;
        As[ak + 1][ar] = av.y;
        As[ak + 2][ar] = av.z;
        As[ak + 3][ar] = av.w;
        // --- load B tile (WT rows contiguous, coalesced)
        float4 bv = *reinterpret_cast<const float4*>(WT + (size_t)(k0 + brow) * N + bn + bcol);
        *reinterpret_cast<float4*>(&Bs[brow][bcol]) = bv;
        __syncthreads();
        #pragma unroll
        for (int k = 0; k < 16; ++k) {
            float4 a = *reinterpret_cast<const float4*>(&As[k][ty * 4]);
            float4 b = *reinterpret_cast<const float4*>(&Bs[k][tx * 4]);
            acc[0][0] += a.x * b.x; acc[0][1] += a.x * b.y; acc[0][2] += a.x * b.z; acc[0][3] += a.x * b.w;
            acc[1][0] += a.y * b.x; acc[1][1] += a.y * b.y; acc[1][2] += a.y * b.z; acc[1][3] += a.y * b.w;
            acc[2][0] += a.z * b.x; acc[2][1] += a.z * b.y; acc[2][2] += a.z * b.z; acc[2][3] += a.z * b.w;
            acc[3][0] += a.w * b.x; acc[3][1] += a.w * b.y; acc[3][2] += a.w * b.z; acc[3][3] += a.w * b.w;
        }
        __syncthreads();
    }
    // --- epilogue
    #pragma unroll
    for (int i = 0; i < 4; i++) {
        int row = bm + ty * 4 + i;
        if (row < M) {
            float4 addv = make_float4(0.f, 0.f, 0.f, 0.f);
            if (Rm)        addv = *reinterpret_cast<const float4*>(Rm + (size_t)row * N + bn + tx * 4);
            else if (bias) addv = *reinterpret_cast<const float4*>(bias + bn + tx * 4);
            float4 o;
            o.x = acc[i][0] + addv.x;
            o.y = acc[i][1] + addv.y;
            o.z = acc[i][2] + addv.z;
            o.w = acc[i][3] + addv.w;
            *reinterpret_cast<float4*>(G + (size_t)row * N + bn + tx * 4) = o;
        }
    }
}

// ---------------- pointwise LSTM cell update --------------------------------
__global__ void lstm_update(int M, int Hd,
                            const float* __restrict__ G,
                            float* __restrict__ c, float* __restrict__ h,
                            float* __restrict__ rec, int rec_stride) {
    int idx = blockIdx.x * blockDim.x + threadIdx.x;
    if (idx >= M * Hd) return;
    int m = idx / Hd;
    int u = idx - m * Hd;
    const float* g = G + (size_t)m * 4 * Hd;
    float gi = g[u], gf = g[Hd + u], gg = g[2 * Hd + u], go = g[3 * Hd + u];
    float cc = sigf(gf) * c[idx] + sigf(gi) * tanhf(gg);
    c[idx] = cc;
    float hh = sigf(go) * tanhf(cc);
    h[idx] = hh;
    if (rec) rec[(size_t)m * rec_stride + u] = hh;
}

// ---------------- persistent inner LSTM (batch 32, 1 block per sequence) ----
__global__ void __launch_bounds__(256)
inner_lstm(const float* __restrict__ xw, int xw_block_stride, int xw_step_stride,
           const float4* __restrict__ wp,
           float* __restrict__ out_c, float* __restrict__ out_h, int steps) {
    __shared__ float h[HDIM];
    int b = blockIdx.x;
    int u = threadIdx.x;
    float c = 0.0f;
    h[u] = 0.0f;
    __syncthreads();
    const float* xwb = xw + (size_t)b * xw_block_stride;
    for (int s = 0; s < steps; ++s) {
        float g0 = xwb[u];
        float g1 = xwb[256 + u];
        float g2 = xwb[512 + u];
        float g3 = xwb[768 + u];
        #pragma unroll 8
        for (int k = 0; k < HDIM; ++k) {
            float hk = h[k];
            float4 w = wp[(k << 8) + u];
            g0 += hk * w.x;
            g1 += hk * w.y;
            g2 += hk * w.z;
            g3 += hk * w.w;
        }
        float cc = sigf(g1) * c + sigf(g0) * tanhf(g2);
        c = cc;
        float hh = sigf(g3) * tanhf(cc);
        __syncthreads();          // all reads of old h done
        h[u] = hh;
        __syncthreads();          // new h visible
        if (out_h) out_h[((size_t)b * steps + s) * HDIM + u] = hh;
        xwb += xw_step_stride;
    }
    if (out_c) out_c[b * HDIM + u] = c;
}

// ---------------- host orchestration ----------------------------------------
extern "C" void kernel_launch(void* const* d_in, const int* in_sizes, int n_in,
                              void* d_out, int out_size) {
    const float* inp    = (const float*)d_in[0];
    const float* oe_wih = (const float*)d_in[1];
    const float* oe_whh = (const float*)d_in[2];
    const float* oe_bih = (const float*)d_in[3];
    const float* oe_bhh = (const float*)d_in[4];
    const float* ie_wih = (const float*)d_in[5];
    const float* ie_whh = (const float*)d_in[6];
    const float* ie_bih = (const float*)d_in[7];
    const float* ie_bhh = (const float*)d_in[8];
    const float* id_wih = (const float*)d_in[9];
    const float* id_whh = (const float*)d_in[10];
    const float* id_bih = (const float*)d_in[11];
    const float* id_bhh = (const float*)d_in[12];
    const float* od_wih = (const float*)d_in[13];
    const float* od_whh = (const float*)d_in[14];
    const float* od_bih = (const float*)d_in[15];
    const float* od_bhh = (const float*)d_in[16];
    float* out = (float*)d_out;

    void* p;
    cudaGetSymbolAddress(&p, g_xT);      float* xT      = (float*)p;
    cudaGetSymbolAddress(&p, g_rec);     float* rec     = (float*)p;
    cudaGetSymbolAddress(&p, g_gates);   float* gates   = (float*)p;
    cudaGetSymbolAddress(&p, g_h);       float* h1      = (float*)p;
    cudaGetSymbolAddress(&p, g_c);       float* c1      = (float*)p;
    cudaGetSymbolAddress(&p, g_xw_ie);   float* xw_ie   = (float*)p;
    cudaGetSymbolAddress(&p, g_bot);     float* bot     = (float*)p;
    cudaGetSymbolAddress(&p, g_xw_id);   float* xw_id   = (float*)p;
    cudaGetSymbolAddress(&p, g_dec);     float* decb    = (float*)p;
    cudaGetSymbolAddress(&p, g_xw_od);   float* xw_od   = (float*)p;
    cudaGetSymbolAddress(&p, g_h2);      float* h2      = (float*)p;
    cudaGetSymbolAddress(&p, g_c2);      float* c2      = (float*)p;
    cudaGetSymbolAddress(&p, g_oe_wT);   float* oe_wT   = (float*)p;
    cudaGetSymbolAddress(&p, g_oe_b);    float* oe_b    = (float*)p;
    cudaGetSymbolAddress(&p, g_ie_wihT); float* ie_wihT = (float*)p;
    cudaGetSymbolAddress(&p, g_ie_b);    float* ie_b    = (float*)p;
    cudaGetSymbolAddress(&p, g_id_wihT); float* id_wihT = (float*)p;
    cudaGetSymbolAddress(&p, g_id_b);    float* id_b    = (float*)p;
    cudaGetSymbolAddress(&p, g_od_wihT); float* od_wihT = (float*)p;
    cudaGetSymbolAddress(&p, g_od_whhT); float* od_whhT = (float*)p;
    cudaGetSymbolAddress(&p, g_od_b);    float* od_b    = (float*)p;
    cudaGetSymbolAddress(&p, g_ie_wp);   float4* ie_wp  = (float4*)p;
    cudaGetSymbolAddress(&p, g_id_wp);   float4* id_wp  = (float4*)p;

    dim3 tb(32, 8);

    // ---- prep: fused biases, transposed weights, packed recurrent weights
    prep_biases<<<4, 256>>>(oe_bih, oe_bhh, ie_bih, ie_bhh, id_bih, id_bhh,
                            od_bih, od_bhh, oe_b, ie_b, id_b, od_b);
    btrans<<<dim3(4, 32, 1), tb>>>(oe_wT,               oe_wih, 1024, 128);
    btrans<<<dim3(8, 32, 1), tb>>>(oe_wT + 128 * 1024,  oe_whh, 1024, 256);
    btrans<<<dim3(8, 32, 1), tb>>>(ie_wihT,             ie_wih, 1024, 256);
    btrans<<<dim3(8, 32, 1), tb>>>(id_wihT,             id_wih, 1024, 256);
    btrans<<<dim3(8, 16, 1), tb>>>(od_wihT,             od_wih,  512, 256);
    btrans<<<dim3(4, 16, 1), tb>>>(od_whhT,             od_whh,  512, 128);
    pack_whh<<<256, 256>>>(ie_wp, ie_whh);
    pack_whh<<<256, 256>>>(id_wp, id_whh);

    // ---- input transpose (B,F,T) -> (B,T,F)
    btrans<<<dim3(75, 4, B_), tb>>>(xT, inp, FBINS, TTOT);

    // ---- outer encoder: 24 fused steps, state (3200,256)
    cudaMemsetAsync(h1, 0, (size_t)BS_ * HDIM * sizeof(float), 0);
    cudaMemsetAsync(c1, 0, (size_t)BS_ * HDIM * sizeof(float), 0);
    for (int t = 0; t < SEG_; ++t) {
        gemm_gates<<<dim3(16, 50), 256>>>(BS_, 1024,
                                          xT + t * FBINS, SEG_ * FBINS, FBINS,
                                          h1, HDIM, HDIM,
                                          oe_wT, oe_b, nullptr, gates);
        lstm_update<<<(BS_ * HDIM + 255) / 256, 256>>>(BS_, HDIM, gates, c1, h1, nullptr, 0);
    }

    // ---- inner encoder: xw precompute + persistent 100-step LSTM -> bottleneck
    gemm_gates<<<dim3(16, 50), 256>>>(BS_, 1024, c1, HDIM, HDIM,
                                      nullptr, 0, 0, ie_wihT, ie_b, nullptr, xw_ie);
    inner_lstm<<<B_, 256>>>(xw_ie, SSEG * 1024, 1024, ie_wp, bot, nullptr, SSEG);

    // ---- inner decoder: constant input per step
    gemm_gates<<<dim3(16, 1), 256>>>(B_, 1024, bot, HDIM, HDIM,
                                     nullptr, 0, 0, id_wihT, id_b, nullptr, xw_id);
    inner_lstm<<<B_, 256>>>(xw_id, 1024, 0, id_wp, nullptr, decb, SSEG);

    // ---- outer decoder: input constant per segment -> xw_od once, then 24 steps
    gemm_gates<<<dim3(8, 50), 256>>>(BS_, 512, decb, HDIM, HDIM,
                                     nullptr, 0, 0, od_wihT, od_b, nullptr, xw_od);
    cudaMemsetAsync(h2, 0, (size_t)BS_ * FBINS * sizeof(float), 0);
    cudaMemsetAsync(c2, 0, (size_t)BS_ * FBINS * sizeof(float), 0);
    for (int t = 0; t < SEG_; ++t) {
        gemm_gates<<<dim3(8, 50), 256>>>(BS_, 512,
                                         h2, FBINS, FBINS,
                                         nullptr, 0, 0,
                                         od_whhT, nullptr, xw_od, gates);
        lstm_update<<<(BS_ * FBINS + 255) / 256, 256>>>(BS_, FBINS, gates, c2, h2,
                                                        rec + t * FBINS, SEG_ * FBINS);
    }

    // ---- final transpose (B,T,F) -> (B,F,T)
    btrans<<<dim3(4, 75, B_), tb>>>(out, rec, TTOT, FBINS);
}